// round 8
// baseline (speedup 1.0000x reference)
#include <cuda_runtime.h>
#include <cuda_bf16.h>

#define IMG_W 416
#define IMG_H 416
#define NCH   3
#define TPB   256
#define STRIPS 32
#define SROWS  13                    // 416 / 32
#define QROW   104                   // float4 quads per row
#define CS     (IMG_W * IMG_H)       // 173056
#define CS4    (CS / 4)              // 43264
#define PB     8                     // patch-role blocks per sample
#define MAXN  256

__device__ float4 g_th[MAXN][2];     // t00,t01,t02,t10 | t11,t12,-,-
__device__ int4   g_box[MAXN];       // qx0, qx1, by, bye (quad-aligned x, inclusive)

// ---------------------------------------------------------------------------
// Prep: one thread per sample computes theta + quad-aligned output bbox.
// ---------------------------------------------------------------------------
__global__ void prep_kernel(const float* __restrict__ bb,
                            const float* __restrict__ angle,
                            const int*   __restrict__ pos_ptr,
                            int N) {
    int n = threadIdx.x;
    if (n >= N) return;

    float patch_ori = 300.0f;
    if (pos_ptr) {
        int pi = pos_ptr[0];
        patch_ori = (pi > 0 && pi < 1000000) ? (float)pi : __int_as_float(pi);
    }
    float x1 = bb[n * 6 + 0];
    float y1 = bb[n * 6 + 1];
    float x2 = bb[n * 6 + 2];
    float y2 = bb[n * 6 + 3];

    float bwv = (x2 - x1) * (float)IMG_W;
    float bhv = (y2 - y1) * (float)IMG_H;
    float cx  = (x1 + x2) * 0.5f;
    float cy  = (y1 + y2) * 0.5f - (y2 - y1) * 0.1f;
    float tx  = (0.5f - cx) * 2.0f;
    float ty  = (0.5f - cy) * 2.0f;
    float target = 0.2f * sqrtf(bwv * bwv + bhv * bhv);
    float scale  = __fdiv_rn(target, patch_ori);

    float a = angle[n];
    float s = sinf(a);
    float c = cosf(a);

    float t00 = __fdiv_rn(c, scale);
    float t01 = __fdiv_rn(s, scale);
    float t02 = __fdiv_rn(tx * c + ty * s, scale);
    float t10 = __fdiv_rn(-s, scale);
    float t11 = __fdiv_rn(c, scale);
    float t12 = __fdiv_rn(-tx * s + ty * c, scale);

    g_th[n][0] = make_float4(t00, t01, t02, t10);
    g_th[n][1] = make_float4(t11, t12, 0.f, 0.f);

    // Pixel-space map constants
    float cx2 = 207.5f - 207.5f * t00 - 207.5f * t01 + 208.0f * t02;
    float cy2 = 207.5f - 207.5f * t10 - 207.5f * t11 + 208.0f * t12;

    // Output-space bbox = preimage of source square [-1,416]^2
    float det  = t00 * t11 - t01 * t10;
    float rdet = __fdiv_rn(1.0f, det);
    float xmin = 1e9f, xmax = -1e9f, ymin = 1e9f, ymax = -1e9f;
#pragma unroll
    for (int k = 0; k < 4; k++) {
        float u  = (k & 1) ? 416.0f : -1.0f;
        float v  = (k & 2) ? 416.0f : -1.0f;
        float du = u - cx2;
        float dv = v - cy2;
        float px = (t11 * du - t01 * dv) * rdet;
        float py = (t00 * dv - t10 * du) * rdet;
        xmin = fminf(xmin, px); xmax = fmaxf(xmax, px);
        ymin = fminf(ymin, py); ymax = fmaxf(ymax, py);
    }
    int bx0 = max(0, (int)floorf(xmin) - 2);
    int by0 = max(0, (int)floorf(ymin) - 2);
    int bx1 = min(IMG_W - 1, (int)ceilf(xmax) + 2);
    int by1 = min(IMG_H - 1, (int)ceilf(ymax) + 2);

    int4 bx;
    if (bx1 >= bx0 && by1 >= by0) {
        bx = make_int4(bx0 >> 2, bx1 >> 2, by0, by1);
    } else {
        bx = make_int4(0, -1, 0, -1);   // empty: fill skips nothing, patch exits
    }
    g_box[n] = bx;
}

// ---------------------------------------------------------------------------
// Main: fill role = near-memset (skip bbox quads); patch role = bilinear bbox.
// Roles are spatially disjoint -> no sync, fully concurrent.
// ---------------------------------------------------------------------------
__global__ void __launch_bounds__(TPB, 8)
fused_kernel(const float* __restrict__ img, float* __restrict__ out) {
    const int n = blockIdx.y;
    const int4 B = g_box[n];          // qx0, qx1, by, bye

    if (blockIdx.x < STRIPS) {
        // ---- Fill role: pure zero stores over 13 contiguous rows/channel ----
        const int y0s = blockIdx.x * SROWS;
        float4* cb0 = (float4*)(out + (size_t)n * NCH * CS) + y0s * QROW;
        const float4 z = make_float4(0.f, 0.f, 0.f, 0.f);
#pragma unroll 2
        for (int i = threadIdx.x; i < SROWS * QROW; i += TPB) {
            int r = i / QROW;
            int q = i - r * QROW;
            int y = y0s + r;
            bool skip = (y >= B.z) && (y <= B.w) && (q >= B.x) && (q <= B.y);
            if (!skip) {
                cb0[i]           = z;
                cb0[i + CS4]     = z;
                cb0[i + 2 * CS4] = z;
            }
        }
        return;
    }

    // ---- Patch role: exclusively own the bbox quad-rectangle ----
    if (B.y < B.x) return;
    const int pb = blockIdx.x - STRIPS;          // 0..PB-1
    const int nq = B.y - B.x + 1;
    const int nr = B.w - B.z + 1;
    const int total = nq * nr;

    const float4 th0 = g_th[n][0];
    const float4 th1 = g_th[n][1];
    const float t00 = th0.x, t01 = th0.y, t02 = th0.z;
    const float t10 = th0.w, t11 = th1.x, t12 = th1.y;

    const float* base = img + (size_t)n * NCH * CS;
    float* obase = out + (size_t)n * NCH * CS;

    for (int t = pb * TPB + threadIdx.x; t < total; t += PB * TPB) {
        const int r  = t / nq;
        const int q  = B.x + (t - r * nq);
        const int yy = B.z + r;
        const int xbase = q * 4;

        const float ysv = __fdiv_rn(2.0f * (float)yy + 1.0f, (float)IMG_W) - 1.0f;
        const float Cx = fmaf(208.0f, fmaf(t01, ysv, t02), fmaf(-207.5f, t00, 207.5f));
        const float Cy = fmaf(208.0f, fmaf(t11, ysv, t12), fmaf(-207.5f, t10, 207.5f));

        float acc0[4], acc1[4], acc2[4];
#pragma unroll
        for (int p = 0; p < 4; p++) {
            const float xf = (float)(xbase + p);
            const float ix = fmaf(t00, xf, Cx);
            const float iy = fmaf(t10, xf, Cy);

            float fx0 = floorf(ix), fy0 = floorf(iy);
            int   x0  = (int)fx0,   y0  = (int)fy0;
            float wx1 = ix - fx0,   wy1 = iy - fy0;
            float wx0 = 1.0f - wx1, wy0 = 1.0f - wy1;

            bool vx0 = (x0 >= 0)  && (x0 < IMG_W);
            bool vx1 = (x0 >= -1) && (x0 < IMG_W - 1);
            bool vy0 = (y0 >= 0)  && (y0 < IMG_H);
            bool vy1 = (y0 >= -1) && (y0 < IMG_H - 1);

            float w00 = (vx0 && vy0) ? wx0 * wy0 : 0.0f;
            float w10 = (vx1 && vy0) ? wx1 * wy0 : 0.0f;
            float w01 = (vx0 && vy1) ? wx0 * wy1 : 0.0f;
            float w11 = (vx1 && vy1) ? wx1 * wy1 : 0.0f;

            float a0 = 0.f, a1 = 0.f, a2 = 0.f;
            int i00 = y0 * IMG_W + x0;
            if (w00 != 0.0f) {
                a0 = fmaf(w00, __ldg(base + i00), a0);
                a1 = fmaf(w00, __ldg(base + CS + i00), a1);
                a2 = fmaf(w00, __ldg(base + 2 * CS + i00), a2);
            }
            if (w10 != 0.0f) {
                int i = i00 + 1;
                a0 = fmaf(w10, __ldg(base + i), a0);
                a1 = fmaf(w10, __ldg(base + CS + i), a1);
                a2 = fmaf(w10, __ldg(base + 2 * CS + i), a2);
            }
            if (w01 != 0.0f) {
                int i = i00 + IMG_W;
                a0 = fmaf(w01, __ldg(base + i), a0);
                a1 = fmaf(w01, __ldg(base + CS + i), a1);
                a2 = fmaf(w01, __ldg(base + 2 * CS + i), a2);
            }
            if (w11 != 0.0f) {
                int i = i00 + IMG_W + 1;
                a0 = fmaf(w11, __ldg(base + i), a0);
                a1 = fmaf(w11, __ldg(base + CS + i), a1);
                a2 = fmaf(w11, __ldg(base + 2 * CS + i), a2);
            }
            acc0[p] = a0;
            acc1[p] = a1;
            acc2[p] = a2;
        }

        const int o = yy * IMG_W + xbase;
        *(float4*)(obase + o)          = make_float4(acc0[0], acc0[1], acc0[2], acc0[3]);
        *(float4*)(obase + o + CS)     = make_float4(acc1[0], acc1[1], acc1[2], acc1[3]);
        *(float4*)(obase + o + 2 * CS) = make_float4(acc2[0], acc2[1], acc2[2], acc2[3]);
    }
}

extern "C" void kernel_launch(void* const* d_in, const int* in_sizes, int n_in,
                              void* d_out, int out_size) {
    const float* img = (const float*)d_in[0];   // adv_patch_batch (B,L,C,H,W) f32
    const float* bb  = (const float*)d_in[1];   // bboxes_batch (B,L,6) f32
    const float* ang = (const float*)d_in[2];   // angle (B*L,) f32
    const int*   pos = (n_in > 3) ? (const int*)d_in[3] : nullptr;

    int N = in_sizes[2];                        // B*L = 128
    if (N > MAXN) N = MAXN;

    prep_kernel<<<1, ((N + 31) / 32) * 32>>>(bb, ang, pos, N);

    dim3 grid(STRIPS + PB, N);
    fused_kernel<<<grid, TPB>>>(img, (float*)d_out);
}

// round 9
// speedup vs baseline: 1.1217x; 1.1217x over previous
#include <cuda_runtime.h>
#include <cuda_bf16.h>

#define IMG_W 416
#define IMG_H 416
#define NCH   3
#define TPB   256
#define QROW  104                    // float4 quads per row
#define CS    (IMG_W * IMG_H)        // 173056
#define PER_N (IMG_H * QROW)         // 43264 threads per sample (multiple of 32)

__global__ void __launch_bounds__(TPB)
sample_kernel(const float* __restrict__ img,
              const float* __restrict__ bb,
              const float* __restrict__ angle,
              const int*   __restrict__ pos_ptr,
              float* __restrict__ out, int total) {
    const int tid = blockIdx.x * TPB + threadIdx.x;
    if (tid >= total) return;               // total is a multiple of 32

    const int xq = tid % QROW;
    const int t2 = tid / QROW;
    const int y  = t2 % IMG_H;
    const int n  = t2 / IMG_H;              // same n for all lanes of a warp

    // ---- theta: lane 0 computes, warp broadcasts (no smem, no syncthreads) ----
    float t00, t01, t02, t10, t11, t12, Kx, Ky;
    if ((threadIdx.x & 31) == 0) {
        float patch_ori = 300.0f;
        if (pos_ptr) {
            int pi = pos_ptr[0];
            patch_ori = (pi > 0 && pi < 1000000) ? (float)pi : __int_as_float(pi);
        }
        float x1 = bb[n * 6 + 0];
        float y1 = bb[n * 6 + 1];
        float x2 = bb[n * 6 + 2];
        float y2 = bb[n * 6 + 3];

        float bwv = (x2 - x1) * (float)IMG_W;
        float bhv = (y2 - y1) * (float)IMG_H;
        float cx  = (x1 + x2) * 0.5f;
        float cy  = (y1 + y2) * 0.5f - (y2 - y1) * 0.1f;
        float tx  = (0.5f - cx) * 2.0f;
        float ty  = (0.5f - cy) * 2.0f;
        float target = 0.2f * sqrtf(bwv * bwv + bhv * bhv);
        float scale  = __fdiv_rn(target, patch_ori);

        float a = angle[n];
        float s = sinf(a);
        float c = cosf(a);

        t00 = __fdiv_rn(c, scale);
        t01 = __fdiv_rn(s, scale);
        t02 = __fdiv_rn(tx * c + ty * s, scale);
        t10 = __fdiv_rn(-s, scale);
        t11 = __fdiv_rn(c, scale);
        t12 = __fdiv_rn(-tx * s + ty * c, scale);

        // approx pixel-map constants (classification only, 0.5px margin)
        Kx = 207.5f - 207.5f * t00 - 207.5f * t01 + 208.0f * t02;
        Ky = 207.5f - 207.5f * t10 - 207.5f * t11 + 208.0f * t12;
    }
    t00 = __shfl_sync(0xffffffffu, t00, 0);
    t01 = __shfl_sync(0xffffffffu, t01, 0);
    t02 = __shfl_sync(0xffffffffu, t02, 0);
    t10 = __shfl_sync(0xffffffffu, t10, 0);
    t11 = __shfl_sync(0xffffffffu, t11, 0);
    t12 = __shfl_sync(0xffffffffu, t12, 0);
    Kx  = __shfl_sync(0xffffffffu, Kx, 0);
    Ky  = __shfl_sync(0xffffffffu, Ky, 0);

    // ---- quad classification (approx coords + generous margin) ----
    const float yf = (float)y;
    const float Rx = fmaf(t01, yf, Kx);
    const float Ry = fmaf(t11, yf, Ky);
    const int xbase = xq * 4;

    const float ix0 = fmaf(t00, (float)xbase, Rx);
    const float iy0 = fmaf(t10, (float)xbase, Ry);
    const float ix3 = fmaf(t00, (float)(xbase + 3), Rx);
    const float iy3 = fmaf(t10, (float)(xbase + 3), Ry);

    const bool any = (fmaxf(ix0, ix3) > -1.5f) && (fminf(ix0, ix3) < 416.5f) &&
                     (fmaxf(iy0, iy3) > -1.5f) && (fminf(iy0, iy3) < 416.5f);

    const int obase = (n * NCH * IMG_H + y) * IMG_W + xbase;

    if (!any) {
        // Fast path (~99.5%): pure zero writes, no reads.
        const float4 z = make_float4(0.f, 0.f, 0.f, 0.f);
        *(float4*)(out + obase)          = z;
        *(float4*)(out + obase + CS)     = z;
        *(float4*)(out + obase + 2 * CS) = z;
        return;
    }

    // ---- slow path: exact validated arithmetic (rel_err 1.1e-4) ----
    const float ysv = __fdiv_rn(2.0f * yf + 1.0f, (float)IMG_W) - 1.0f;
    const float Cx = fmaf(208.0f, fmaf(t01, ysv, t02), fmaf(-207.5f, t00, 207.5f));
    const float Cy = fmaf(208.0f, fmaf(t11, ysv, t12), fmaf(-207.5f, t10, 207.5f));

    const float* base = img + (size_t)n * NCH * CS;
    float acc0[4], acc1[4], acc2[4];
#pragma unroll
    for (int p = 0; p < 4; p++) {
        const float xf = (float)(xbase + p);
        const float ix = fmaf(t00, xf, Cx);
        const float iy = fmaf(t10, xf, Cy);

        float fx0 = floorf(ix), fy0 = floorf(iy);
        int   x0  = (int)fx0,   y0  = (int)fy0;
        float wx1 = ix - fx0,   wy1 = iy - fy0;
        float wx0 = 1.0f - wx1, wy0 = 1.0f - wy1;

        bool vx0 = (x0 >= 0)  && (x0 < IMG_W);
        bool vx1 = (x0 >= -1) && (x0 < IMG_W - 1);
        bool vy0 = (y0 >= 0)  && (y0 < IMG_H);
        bool vy1 = (y0 >= -1) && (y0 < IMG_H - 1);

        float w00 = (vx0 && vy0) ? wx0 * wy0 : 0.0f;
        float w10 = (vx1 && vy0) ? wx1 * wy0 : 0.0f;
        float w01 = (vx0 && vy1) ? wx0 * wy1 : 0.0f;
        float w11 = (vx1 && vy1) ? wx1 * wy1 : 0.0f;

        float a0 = 0.f, a1 = 0.f, a2 = 0.f;
        int i00 = y0 * IMG_W + x0;
        if (w00 != 0.0f) {
            a0 = fmaf(w00, __ldg(base + i00), a0);
            a1 = fmaf(w00, __ldg(base + CS + i00), a1);
            a2 = fmaf(w00, __ldg(base + 2 * CS + i00), a2);
        }
        if (w10 != 0.0f) {
            int i = i00 + 1;
            a0 = fmaf(w10, __ldg(base + i), a0);
            a1 = fmaf(w10, __ldg(base + CS + i), a1);
            a2 = fmaf(w10, __ldg(base + 2 * CS + i), a2);
        }
        if (w01 != 0.0f) {
            int i = i00 + IMG_W;
            a0 = fmaf(w01, __ldg(base + i), a0);
            a1 = fmaf(w01, __ldg(base + CS + i), a1);
            a2 = fmaf(w01, __ldg(base + 2 * CS + i), a2);
        }
        if (w11 != 0.0f) {
            int i = i00 + IMG_W + 1;
            a0 = fmaf(w11, __ldg(base + i), a0);
            a1 = fmaf(w11, __ldg(base + CS + i), a1);
            a2 = fmaf(w11, __ldg(base + 2 * CS + i), a2);
        }
        acc0[p] = a0;
        acc1[p] = a1;
        acc2[p] = a2;
    }

    *(float4*)(out + obase)          = make_float4(acc0[0], acc0[1], acc0[2], acc0[3]);
    *(float4*)(out + obase + CS)     = make_float4(acc1[0], acc1[1], acc1[2], acc1[3]);
    *(float4*)(out + obase + 2 * CS) = make_float4(acc2[0], acc2[1], acc2[2], acc2[3]);
}

extern "C" void kernel_launch(void* const* d_in, const int* in_sizes, int n_in,
                              void* d_out, int out_size) {
    const float* img = (const float*)d_in[0];   // adv_patch_batch (B,L,C,H,W) f32
    const float* bb  = (const float*)d_in[1];   // bboxes_batch (B,L,6) f32
    const float* ang = (const float*)d_in[2];   // angle (B*L,) f32
    const int*   pos = (n_in > 3) ? (const int*)d_in[3] : nullptr;

    int N = in_sizes[2];                        // B*L = 128
    int total = N * PER_N;

    sample_kernel<<<(total + TPB - 1) / TPB, TPB>>>(img, bb, ang, pos,
                                                    (float*)d_out, total);
}